// round 17
// baseline (speedup 1.0000x reference)
#include <cuda_runtime.h>
#include <cstdint>

// Problem constants: B=512, T=2048, I=4, H=100, O=1
#define HDIM     100
#define TLEN     2048
#define BLOCK_T  320    // 2 groups x (4 main warps + 1 decoupled reducer warp)
#define NBLOCKS  128    // 4 batches per CTA -> 512
#define PADH     128    // h row stride in smem (floats); pad stays 0
#define KH       52     // columns per K-half (100 padded to 104)
#define RING     8      // h ring depth (slot k holds h_k, k mod 8)

// ---- packed fp32x2 ops (Blackwell FFMA2 path, only reachable via PTX) ----
__device__ __forceinline__ unsigned long long ffma2(unsigned long long a,
                                                    unsigned long long b,
                                                    unsigned long long c) {
    unsigned long long d;
    asm("fma.rn.f32x2 %0, %1, %2, %3;" : "=l"(d) : "l"(a), "l"(b), "l"(c));
    return d;
}
__device__ __forceinline__ unsigned long long fadd2(unsigned long long a,
                                                    unsigned long long b) {
    unsigned long long d;
    asm("add.rn.f32x2 %0, %1, %2;" : "=l"(d) : "l"(a), "l"(b));
    return d;
}
__device__ __forceinline__ float hsum2(unsigned long long a) {
    unsigned int lo, hi;
    asm("mov.b64 {%0, %1}, %2;" : "=r"(lo), "=r"(hi) : "l"(a));
    return __uint_as_float(lo) + __uint_as_float(hi);
}

// tanh(x) = 1 - 2/(exp2(2*log2e*x)+1)  (validated rel_err ~1e-6 over 2048 steps)
__device__ __forceinline__ float fast_tanh(float x) {
    float e, r;
    asm("ex2.approx.f32 %0, %1;" : "=f"(e) : "f"(x * 2.8853900817779268f));
    asm("rcp.approx.f32 %0, %1;" : "=f"(r) : "f"(e + 1.0f));
    return fmaf(-2.0f, r, 1.0f);
}

// mains-only named barrier (4 whole warps = 128 threads per group)
__device__ __forceinline__ void group_bar(int id) {
    asm volatile("bar.sync %0, %1;" :: "r"(id), "n"(128) : "memory");
}

// CTA-scope acquire/release on shared counters (generic addressing)
__device__ __forceinline__ unsigned int ld_acq(const unsigned int* p) {
    unsigned int v;
    asm volatile("ld.acquire.cta.u32 %0, [%1];" : "=r"(v) : "l"(p) : "memory");
    return v;
}
__device__ __forceinline__ void st_rel(unsigned int* p, unsigned int v) {
    asm volatile("st.release.cta.u32 [%0], %1;" :: "l"(p), "r"(v) : "memory");
}

// ============================================================================
// Single persistent kernel. Per 160-thread group: 4 main warps run the R15
// recurrence (2 batches, shared W_hh regs, 2 chains/warp) over an 8-deep
// SMEM h ring; 1 reducer warp trails behind via seq/done counters and writes
// out[b,t] = W_fc . h_{t+1} + b_fc with no coupling into the mains' barrier.
// ============================================================================
__global__ void __launch_bounds__(BLOCK_T, 1)
crnn_kernel(const float* __restrict__ x,      // [512, 2048, 4]
            const float* __restrict__ W_ih,   // [100, 4]
            const float* __restrict__ W_hh,   // [100, 100]
            const float* __restrict__ W_fc,   // [1, 100]
            const float* __restrict__ b_fc,   // [1]
            float* __restrict__ out)          // [512, 2048, 1]
{
    // h ring: hbuf[slot][group][local batch][PADH]  (16 KB)
    __shared__ __align__(16) float hbuf[RING][2][2][PADH];
    // ctr[0..1] = seq per group (mains -> reducer): steps published
    // ctr[2..3] = done per group (reducer -> mains): steps consumed
    __shared__ unsigned int ctr[4];

    const int tid  = threadIdx.x;
    const int wid  = tid >> 5;
    const int lane = tid & 31;
    const int g    = (wid >= 5);         // group 0..1
    const int wgl  = wid - 5 * g;        // warp in group 0..4 (4 = reducer)
    const int bg0  = blockIdx.x * 4 + g * 2;
    const int bg1  = bg0 + 1;
    const int barid = 1 + g;

    // zero the whole ring (h_0 = 0 in slot 0; pads [100,128) stay 0 forever)
    for (int i = tid; i < RING * 2 * 2 * PADH; i += BLOCK_T)
        ((float*)hbuf)[i] = 0.0f;
    if (tid < 4) ctr[tid] = 0u;
    __syncthreads();                     // init barrier (block-wide, once)

    if (wgl < 4) {
        // ================= MAIN WARPS: the recurrence (R15 core) ==========
        const int praw  = wgl * 16 + (lane >> 1);   // row-pair index
        const int j     = lane & 1;                  // K-half 0/1
        const bool active = (praw < 50);
        const int pc    = active ? praw : 49;        // clamp for safe loads
        const int row0  = 2 * pc;
        const int own   = row0 + j;                  // row this thread owns

        // W_hh: 2 rows x 52-col half -> 104 regs (shared by both batches)
        unsigned long long w0[26], w1[26];
        {
            const ulonglong2* r0p =
                reinterpret_cast<const ulonglong2*>(W_hh + row0 * HDIM + KH * j);
            const ulonglong2* r1p =
                reinterpret_cast<const ulonglong2*>(W_hh + (row0 + 1) * HDIM + KH * j);
            #pragma unroll
            for (int k = 0; k < 13; k++) {
                ulonglong2 v = r0p[k];
                w0[2 * k] = v.x;  w0[2 * k + 1] = v.y;
            }
            #pragma unroll
            for (int k = 0; k < 12; k++) {
                ulonglong2 v = r1p[k];
                w1[2 * k] = v.x;  w1[2 * k + 1] = v.y;
            }
            // row 99's upper half, last pair: matching h is the zero pad
            if (pc == 49 && j == 1) {
                w1[24] = 0ull; w1[25] = 0ull;
            } else {
                ulonglong2 v = r1p[12];
                w1[24] = v.x; w1[25] = v.y;
            }
        }

        const float4 wih = *reinterpret_cast<const float4*>(W_ih + own * 4);

        const float4* xp0 = reinterpret_cast<const float4*>(x) + (size_t)bg0 * TLEN;
        const float4* xp1 = reinterpret_cast<const float4*>(x) + (size_t)bg1 * TLEN;

        // ring base pointers (slot stride = 2*2*PADH floats)
        const float* rb0 = &hbuf[0][g][0][KH * j];   // read base, batch 0
        const float* rb1 = &hbuf[0][g][1][KH * j];   // read base, batch 1
        float*       wb0 = &hbuf[0][g][0][own];      // write base, batch 0
        float*       wb1 = &hbuf[0][g][1][own];      // write base, batch 1
        const int    sstr = 2 * 2 * PADH;            // floats per ring slot

        float4 xc0 = xp0[0];
        float4 xc1 = xp1[0];

        #pragma unroll 1
        for (int t = 0; t < TLEN; t++) {
            // backpressure: slot (t+1)&7 holds h_{t-7}; reducer must have
            // consumed it (done >= t-7). Never triggers in steady state.
            if (t >= RING) {
                while ((int)ld_acq(&ctr[2 + g]) < t - (RING - 1))
                    __nanosleep(64);
            }

            const int tn = (t < TLEN - 1) ? (t + 1) : t;
            float4 xn0 = xp0[tn];
            float4 xn1 = xp1[tn];

            // input projections (independent of h)
            float xpj0 = xc0.x * wih.x;
            xpj0 = fmaf(xc0.y, wih.y, xpj0);
            xpj0 = fmaf(xc0.z, wih.z, xpj0);
            xpj0 = fmaf(xc0.w, wih.w, xpj0);
            float xpj1 = xc1.x * wih.x;
            xpj1 = fmaf(xc1.y, wih.y, xpj1);
            xpj1 = fmaf(xc1.z, wih.z, xpj1);
            xpj1 = fmaf(xc1.w, wih.w, xpj1);

            // two interleaved matvecs over this thread's K-half
            unsigned long long a00 = 0ull, a01 = 0ull, a10 = 0ull, a11 = 0ull;
            unsigned long long b00 = 0ull, b01 = 0ull, b10 = 0ull, b11 = 0ull;
            const int rs = (t & (RING - 1)) * sstr;
            const ulonglong2* hva = reinterpret_cast<const ulonglong2*>(rb0 + rs);
            const ulonglong2* hvb = reinterpret_cast<const ulonglong2*>(rb1 + rs);
            #pragma unroll
            for (int k = 0; k < 13; k++) {
                ulonglong2 ha  = hva[k];
                ulonglong2 hbv = hvb[k];
                a00 = ffma2(ha.x,  w0[2 * k],     a00);
                b00 = ffma2(hbv.x, w0[2 * k],     b00);
                a01 = ffma2(ha.y,  w0[2 * k + 1], a01);
                b01 = ffma2(hbv.y, w0[2 * k + 1], b01);
                a10 = ffma2(ha.x,  w1[2 * k],     a10);
                b10 = ffma2(hbv.x, w1[2 * k],     b10);
                a11 = ffma2(ha.y,  w1[2 * k + 1], a11);
                b11 = ffma2(hbv.y, w1[2 * k + 1], b11);
            }

            // half-dot sums; combine with partner lane (other K-half)
            float s00 = hsum2(fadd2(a00, a01));
            float s01 = hsum2(fadd2(a10, a11));
            float s10 = hsum2(fadd2(b00, b01));
            float s11 = hsum2(fadd2(b10, b11));
            float u00 = s00 + __shfl_xor_sync(0xFFFFFFFFu, s00, 1);
            float u01 = s01 + __shfl_xor_sync(0xFFFFFFFFu, s01, 1);
            float u10 = s10 + __shfl_xor_sync(0xFFFFFFFFu, s10, 1);
            float u11 = s11 + __shfl_xor_sync(0xFFFFFFFFu, s11, 1);

            const float hn0 = fast_tanh((j ? u01 : u00) + xpj0);
            const float hn1 = fast_tanh((j ? u11 : u10) + xpj1);

            // publish h_{t+1} into ring slot (t+1)&7 (pre-barrier: absorbed)
            const int ws = ((t + 1) & (RING - 1)) * sstr;
            if (active) {
                wb0[ws] = hn0;
                wb1[ws] = hn1;
            }

            group_bar(barid);            // mains of this group: h_{t+1} ready

            // hand h_{t+1} to the reducer (release store, fire-and-forget)
            if (wgl == 0 && lane == 0)
                st_rel(&ctr[g], (unsigned int)(t + 1));

            xc0 = xn0;
            xc1 = xn1;
        }
    } else {
        // ============ REDUCER WARP (decoupled): output projection =========
        // lane < 25 owns h[4*lane .. 4*lane+4) (25*4 = 100 exactly)
        const bool ract = (lane < 25);
        float4 wf = make_float4(0.f, 0.f, 0.f, 0.f);
        if (ract)
            wf = *reinterpret_cast<const float4*>(W_fc + lane * 4);
        const float bias = b_fc[0];

        float* op0 = out + (size_t)bg0 * TLEN;
        float* op1 = out + (size_t)bg1 * TLEN;

        #pragma unroll 1
        for (int t = 0; t < TLEN; t++) {
            // wait until mains published h_{t+1} (seq >= t+1)
            while ((int)ld_acq(&ctr[g]) < t + 1)
                __nanosleep(48);

            const int lb = (t + 1) & (RING - 1);
            float s0 = 0.0f, s1 = 0.0f;
            if (ract) {
                float4 h0 = *reinterpret_cast<const float4*>(&hbuf[lb][g][0][lane * 4]);
                float4 h1 = *reinterpret_cast<const float4*>(&hbuf[lb][g][1][lane * 4]);
                s0 = h0.x * wf.x;
                s1 = h1.x * wf.x;
                s0 = fmaf(h0.y, wf.y, s0);
                s1 = fmaf(h1.y, wf.y, s1);
                s0 = fmaf(h0.z, wf.z, s0);
                s1 = fmaf(h1.z, wf.z, s1);
                s0 = fmaf(h0.w, wf.w, s0);
                s1 = fmaf(h1.w, wf.w, s1);
            }
            s0 += __shfl_xor_sync(0xFFFFFFFFu, s0, 1);
            s1 += __shfl_xor_sync(0xFFFFFFFFu, s1, 1);
            s0 += __shfl_xor_sync(0xFFFFFFFFu, s0, 2);
            s1 += __shfl_xor_sync(0xFFFFFFFFu, s1, 2);
            s0 += __shfl_xor_sync(0xFFFFFFFFu, s0, 4);
            s1 += __shfl_xor_sync(0xFFFFFFFFu, s1, 4);
            s0 += __shfl_xor_sync(0xFFFFFFFFu, s0, 8);
            s1 += __shfl_xor_sync(0xFFFFFFFFu, s1, 8);
            s0 += __shfl_xor_sync(0xFFFFFFFFu, s0, 16);
            s1 += __shfl_xor_sync(0xFFFFFFFFu, s1, 16);
            if (lane == 0)
                op0[t] = s0 + bias;
            else if (lane == 1)          // lane 1 also holds the full sum
                op1[t] = s1 + bias;

            // all lanes' reads of slot lb done -> release it to the mains
            __syncwarp();
            if (lane == 0)
                st_rel(&ctr[2 + g], (unsigned int)(t + 1));
        }
    }
}

extern "C" void kernel_launch(void* const* d_in, const int* in_sizes, int n_in,
                              void* d_out, int out_size) {
    const float* x    = (const float*)d_in[0];  // [512,2048,4]
    const float* W_ih = (const float*)d_in[1];  // [100,4]
    const float* W_hh = (const float*)d_in[2];  // [100,100]
    const float* W_fc = (const float*)d_in[3];  // [1,100]
    const float* b_fc = (const float*)d_in[4];  // [1]
    float* out = (float*)d_out;                 // [512,2048,1]

    crnn_kernel<<<NBLOCKS, BLOCK_T>>>(x, W_ih, W_hh, W_fc, b_fc, out);
}